// round 8
// baseline (speedup 1.0000x reference)
#include <cuda_runtime.h>
#include <cuda_bf16.h>
#include <cstdint>
#include <cstddef>

// ---------------------------------------------------------------------------
// SpatialSelfAttention on GB300 — bf16 mma.sync engine + fused flash attention.
// GN -> transpose -> fused QK proj -> V proj -> flash(S,softmax,PV) -> O proj.
// Layouts (all K-major x K-major):
//   hn_T    : [n, c] bf16
//   qk      : [n, 1024] bf16  (q = cols 0..511, k = cols 512..1023)
//   v       : [c, 4096] bf16
//   oT      : [n, c] bf16
// ---------------------------------------------------------------------------

namespace {
constexpr int kB = 8;
constexpr int kC = 512;
constexpr int kN = 4096;
constexpr int kG = 32;
constexpr int kCPG = kC / kG;
constexpr size_t kCN = (size_t)kC * kN;
constexpr int kSmemBytes = 2 * 32768;       // gemm double buffers
constexpr int kFlashSmem = 206848;          // Q64K K2x32K V64K P8K red2K
}

// Scratch
__device__ float          g_hn [kB * kCN];
__device__ __nv_bfloat16  g_hnT[kB * kCN];
__device__ __nv_bfloat16  g_qk [kB * (size_t)kN * 1024];
__device__ __nv_bfloat16  g_v  [kB * kCN];
__device__ __nv_bfloat16  g_oT [kB * kCN];
__device__ __nv_bfloat16  g_wr [4 * kC * kC];   // wq | wk | wv | wo (bf16)
__device__ float          g_bqk[1024];

// ---------------------------------------------------------------------------
__device__ __forceinline__ uint32_t smem_u32(const void* p) {
    uint32_t a;
    asm("{ .reg .u64 t; cvta.to.shared.u64 t, %1; cvt.u32.u64 %0, t; }"
        : "=r"(a) : "l"(p));
    return a;
}
__device__ __forceinline__ void cp_async16(uint32_t dst, const void* src) {
    asm volatile("cp.async.cg.shared.global [%0], [%1], 16;"
                 :: "r"(dst), "l"(src));
}
__device__ __forceinline__ void ldsm_x4(uint32_t* r, uint32_t addr) {
    asm volatile("ldmatrix.sync.aligned.m8n8.x4.shared.b16 {%0,%1,%2,%3}, [%4];"
                 : "=r"(r[0]), "=r"(r[1]), "=r"(r[2]), "=r"(r[3]) : "r"(addr));
}
__device__ __forceinline__ void mma_bf16(float* d, const uint32_t* a,
                                         const uint32_t* b) {
    asm volatile(
        "mma.sync.aligned.m16n8k16.row.col.f32.bf16.bf16.f32 "
        "{%0,%1,%2,%3}, {%4,%5,%6,%7}, {%8,%9}, {%0,%1,%2,%3};"
        : "+f"(d[0]), "+f"(d[1]), "+f"(d[2]), "+f"(d[3])
        : "r"(a[0]), "r"(a[1]), "r"(a[2]), "r"(a[3]), "r"(b[0]), "r"(b[1]));
}

// ---------------------------------------------------------------------------
// Generic bf16 GEMM (unchanged engine from R7): D = alpha*A@B^T (+bias)(+resid)
// ---------------------------------------------------------------------------
template <typename OutT, bool BIAS_N, bool BIAS_M, bool RESID>
__global__ __launch_bounds__(256)
void mma_gemm(const __nv_bfloat16* __restrict__ A, int lda, size_t sA,
              const __nv_bfloat16* __restrict__ B, int ldb, size_t sB,
              OutT* __restrict__ C, int ldc, size_t sC,
              int K, float alpha,
              const float* __restrict__ bias,
              const float* __restrict__ resid, size_t sR)
{
    extern __shared__ char smem[];
    const uint32_t base = smem_u32(smem);

    const int tid = threadIdx.x;
    const int wid = tid >> 5;
    const int l   = tid & 31;
    const int wm  = wid & 3;
    const int wn  = wid >> 2;

    A += (size_t)blockIdx.z * sA;
    B += (size_t)blockIdx.z * sB;
    C += (size_t)blockIdx.z * sC;
    if (RESID) resid += (size_t)blockIdx.z * sR;

    const int bm = blockIdx.y * 128;
    const int bn = blockIdx.x * 128;

    const int rowA = (l & 7) + ((l >> 3) & 1) * 8;
    const int jA   = (l >> 4) & 1;
    const int rowB = (l & 7) + ((l >> 4) & 1) * 8;
    const int jB   = (l >> 3) & 1;

    float acc[2][8][4];
    #pragma unroll
    for (int i = 0; i < 2; i++)
        #pragma unroll
        for (int j = 0; j < 8; j++)
            #pragma unroll
            for (int r = 0; r < 4; r++) acc[i][j][r] = 0.f;

    const int nk = K >> 6;

    auto load_tile = [&](int it, int s) {
        const uint32_t aB = base + s * 32768;
        const uint32_t bB = aB + 16384;
        const __nv_bfloat16* ag = A + (size_t)bm * lda + (it << 6);
        const __nv_bfloat16* bg = B + (size_t)bn * ldb + (it << 6);
        #pragma unroll
        for (int i = 0; i < 4; ++i) {
            const int idx = tid + (i << 8);
            const int r = idx >> 3, c = idx & 7;
            const uint32_t so = (uint32_t)(r * 128 + ((c ^ (r & 7)) << 4));
            cp_async16(aB + so, ag + (size_t)r * lda + c * 8);
            cp_async16(bB + so, bg + (size_t)r * ldb + c * 8);
        }
        asm volatile("cp.async.commit_group;" ::: "memory");
    };

    load_tile(0, 0);
    for (int it = 0; it < nk; ++it) {
        if (it + 1 < nk) {
            load_tile(it + 1, (it + 1) & 1);
            asm volatile("cp.async.wait_group 1;" ::: "memory");
        } else {
            asm volatile("cp.async.wait_group 0;" ::: "memory");
        }
        __syncthreads();

        const uint32_t aB = base + (it & 1) * 32768;
        const uint32_t bB = aB + 16384;

        #pragma unroll
        for (int ks = 0; ks < 4; ++ks) {
            uint32_t afr[2][4];
            #pragma unroll
            for (int fm = 0; fm < 2; ++fm) {
                const int row = wm * 32 + fm * 16 + rowA;
                const int ch  = (2 * ks + jA) ^ (row & 7);
                ldsm_x4(afr[fm], aB + (uint32_t)(row * 128 + (ch << 4)));
            }
            uint32_t bfr[8][2];
            #pragma unroll
            for (int f2 = 0; f2 < 4; ++f2) {
                const int row = wn * 64 + f2 * 16 + rowB;
                const int ch  = (2 * ks + jB) ^ (row & 7);
                uint32_t t[4];
                ldsm_x4(t, bB + (uint32_t)(row * 128 + (ch << 4)));
                bfr[f2 * 2][0]     = t[0]; bfr[f2 * 2][1]     = t[1];
                bfr[f2 * 2 + 1][0] = t[2]; bfr[f2 * 2 + 1][1] = t[3];
            }
            #pragma unroll
            for (int fm = 0; fm < 2; ++fm)
                #pragma unroll
                for (int fn = 0; fn < 8; ++fn)
                    mma_bf16(acc[fm][fn], afr[fm], bfr[fn]);
        }
        __syncthreads();
    }

    #pragma unroll
    for (int fm = 0; fm < 2; ++fm) {
        const int r0 = bm + wm * 32 + fm * 16 + (l >> 2);
        #pragma unroll
        for (int half = 0; half < 2; ++half) {
            const int m = r0 + half * 8;
            const float bmv = BIAS_M ? bias[m] : 0.f;
            #pragma unroll
            for (int fn = 0; fn < 8; ++fn) {
                const int col = bn + wn * 64 + fn * 8 + (l & 3) * 2;
                float2 o;
                o.x = acc[fm][fn][half * 2 + 0] * alpha;
                o.y = acc[fm][fn][half * 2 + 1] * alpha;
                if (BIAS_N) { o.x += bias[col]; o.y += bias[col + 1]; }
                if (BIAS_M) { o.x += bmv; o.y += bmv; }
                if (RESID) {
                    const float2 rv = *reinterpret_cast<const float2*>(
                        &resid[(size_t)m * ldc + col]);
                    o.x += rv.x; o.y += rv.y;
                }
                OutT* dst = &C[(size_t)m * ldc + col];
                if constexpr (sizeof(OutT) == 4) {
                    *reinterpret_cast<float2*>(dst) = o;
                } else {
                    __nv_bfloat162 h = __floats2bfloat162_rn(o.x, o.y);
                    *reinterpret_cast<__nv_bfloat162*>(dst) = h;
                }
            }
        }
    }
}

// ---------------------------------------------------------------------------
// Fused flash attention: per CTA 64 queries x full 4096 keys, d = 512.
// 512 threads / 16 warps (4m x 4n). Online softmax; O acc in registers.
// smem: Q 64K | Kbuf0 32K | Kbuf1 32K | V 64K | P 8K | red 2K  = 202K
// ---------------------------------------------------------------------------
__global__ __launch_bounds__(512, 1)
void flash_kernel(const __nv_bfloat16* __restrict__ qk,   // [4096][1024]
                  const __nv_bfloat16* __restrict__ v,    // [512][4096]
                  __nv_bfloat16* __restrict__ o,          // [4096][512]
                  float alpha)
{
    extern __shared__ char smem[];
    const uint32_t sQ  = smem_u32(smem);
    const uint32_t sK0 = sQ + 65536;
    const uint32_t sK1 = sK0 + 32768;
    const uint32_t sV  = sK1 + 32768;
    const uint32_t sP  = sV + 65536;
    float* redmax = reinterpret_cast<float*>(smem + 204800);   // [4][64]
    float* redsum = reinterpret_cast<float*>(smem + 205824);   // [4][64]

    const int tid = threadIdx.x;
    const int wid = tid >> 5, l = tid & 31;
    const int wm = wid & 3, wn = wid >> 2;
    const int q0 = blockIdx.x * 64;

    qk += (size_t)blockIdx.y * kN * 1024;
    v  += (size_t)blockIdx.y * kCN;
    o  += (size_t)blockIdx.y * kCN;

    const int rowA = (l & 7) + ((l >> 3) & 1) * 8;
    const int jA   = (l >> 4) & 1;
    const int rowB = (l & 7) + ((l >> 4) & 1) * 8;
    const int jB   = (l >> 3) & 1;
    const int row0 = wm * 16 + (l >> 2);
    const int row1 = row0 + 8;

    // ---- group 0: load Q (resident) ----
    #pragma unroll
    for (int i = 0; i < 8; ++i) {
        const int idx = tid + i * 512;             // 0..4095
        const int r = idx >> 6, rem = idx & 63, p = rem >> 3, cc = rem & 7;
        cp_async16(sQ + p * 8192 + r * 128 + ((cc ^ (r & 7)) << 4),
                   qk + (size_t)(q0 + r) * 1024 + p * 64 + cc * 8);
    }
    asm volatile("cp.async.commit_group;" ::: "memory");

    auto load_khalf = [&](int j0, int h, uint32_t buf) {
        #pragma unroll
        for (int i = 0; i < 4; ++i) {
            const int idx = tid + i * 512;         // 0..2047
            const int r = idx >> 5, rem = idx & 31, p = rem >> 3, cc = rem & 7;
            cp_async16(buf + p * 8192 + r * 128 + ((cc ^ (r & 7)) << 4),
                       qk + (size_t)(j0 + r) * 1024 + 512 + h * 256 + p * 64 + cc * 8);
        }
        asm volatile("cp.async.commit_group;" ::: "memory");
    };
    auto load_v = [&](int j0) {
        #pragma unroll
        for (int i = 0; i < 8; ++i) {
            const int idx = tid + i * 512;         // 0..4095
            const int c = idx >> 3, ch = idx & 7;
            cp_async16(sV + c * 128 + ((ch ^ (c & 7)) << 4),
                       v + (size_t)c * 4096 + j0 + ch * 8);
        }
        asm volatile("cp.async.commit_group;" ::: "memory");
    };

    load_khalf(0, 0, sK0);                         // K(0) half0

    float oacc[16][4];
    #pragma unroll
    for (int i = 0; i < 16; ++i)
        #pragma unroll
        for (int r = 0; r < 4; ++r) oacc[i][r] = 0.f;
    float m0 = -3.4e38f, m1 = -3.4e38f, l0 = 0.f, l1 = 0.f;

    float sacc[2][4];

    auto s_half = [&](uint32_t kbuf, int ph0) {
        #pragma unroll
        for (int p = 0; p < 4; ++p) {
            const uint32_t Qp = sQ + (ph0 + p) * 8192;
            const uint32_t Kp = kbuf + p * 8192;
            #pragma unroll
            for (int ks = 0; ks < 4; ++ks) {
                uint32_t a[4], t[4];
                {
                    const int row = wm * 16 + rowA;
                    const int ch  = (2 * ks + jA) ^ (row & 7);
                    ldsm_x4(a, Qp + (uint32_t)(row * 128 + (ch << 4)));
                }
                {
                    const int row = wn * 16 + rowB;
                    const int ch  = (2 * ks + jB) ^ (row & 7);
                    ldsm_x4(t, Kp + (uint32_t)(row * 128 + (ch << 4)));
                }
                uint32_t b0[2] = {t[0], t[1]}, b1[2] = {t[2], t[3]};
                mma_bf16(sacc[0], a, b0);
                mma_bf16(sacc[1], a, b1);
            }
        }
    };

    for (int t = 0; t < 64; ++t) {
        const int j0 = t * 64;
        load_khalf(j0, 1, sK1);                    // committed BEFORE V
        load_v(j0);
        asm volatile("cp.async.wait_group 2;" ::: "memory");  // K half0 ready
        __syncthreads();                                       // [A]

        #pragma unroll
        for (int i = 0; i < 2; ++i)
            #pragma unroll
            for (int r = 0; r < 4; ++r) sacc[i][r] = 0.f;

        s_half(sK0, 0);
        asm volatile("cp.async.wait_group 1;" ::: "memory");  // K half1 ready
        __syncthreads();                                       // [B]
        if (t + 1 < 64) load_khalf(j0 + 64, 0, sK0);           // prefetch next
        s_half(sK1, 4);

        // ---- online softmax ----
        #pragma unroll
        for (int i = 0; i < 2; ++i)
            #pragma unroll
            for (int r = 0; r < 4; ++r) sacc[i][r] *= alpha;

        float tmx0 = fmaxf(fmaxf(sacc[0][0], sacc[0][1]),
                           fmaxf(sacc[1][0], sacc[1][1]));
        float tmx1 = fmaxf(fmaxf(sacc[0][2], sacc[0][3]),
                           fmaxf(sacc[1][2], sacc[1][3]));
        tmx0 = fmaxf(tmx0, __shfl_xor_sync(0xffffffffu, tmx0, 1));
        tmx0 = fmaxf(tmx0, __shfl_xor_sync(0xffffffffu, tmx0, 2));
        tmx1 = fmaxf(tmx1, __shfl_xor_sync(0xffffffffu, tmx1, 1));
        tmx1 = fmaxf(tmx1, __shfl_xor_sync(0xffffffffu, tmx1, 2));
        if ((l & 3) == 0) {
            redmax[wn * 64 + row0] = tmx0;
            redmax[wn * 64 + row1] = tmx1;
        }
        __syncthreads();                                       // [C]
        const float tm0 = fmaxf(fmaxf(redmax[row0], redmax[64 + row0]),
                                fmaxf(redmax[128 + row0], redmax[192 + row0]));
        const float tm1 = fmaxf(fmaxf(redmax[row1], redmax[64 + row1]),
                                fmaxf(redmax[128 + row1], redmax[192 + row1]));
        const float mn0 = fmaxf(m0, tm0), mn1 = fmaxf(m1, tm1);
        const float f0 = __expf(m0 - mn0), f1 = __expf(m1 - mn1);
        m0 = mn0; m1 = mn1;
        #pragma unroll
        for (int i = 0; i < 2; ++i) {
            sacc[i][0] = __expf(sacc[i][0] - mn0);
            sacc[i][1] = __expf(sacc[i][1] - mn0);
            sacc[i][2] = __expf(sacc[i][2] - mn1);
            sacc[i][3] = __expf(sacc[i][3] - mn1);
        }
        float ts0 = sacc[0][0] + sacc[0][1] + sacc[1][0] + sacc[1][1];
        float ts1 = sacc[0][2] + sacc[0][3] + sacc[1][2] + sacc[1][3];
        ts0 += __shfl_xor_sync(0xffffffffu, ts0, 1);
        ts0 += __shfl_xor_sync(0xffffffffu, ts0, 2);
        ts1 += __shfl_xor_sync(0xffffffffu, ts1, 1);
        ts1 += __shfl_xor_sync(0xffffffffu, ts1, 2);
        if ((l & 3) == 0) {
            redsum[wn * 64 + row0] = ts0;
            redsum[wn * 64 + row1] = ts1;
        }
        // write P (bf16) to smem — visible after sync [D]
        #pragma unroll
        for (int nf = 0; nf < 2; ++nf) {
            const int col = wn * 16 + nf * 8 + (l & 3) * 2;
            const int chs = col >> 3;
            const __nv_bfloat162 plo = __floats2bfloat162_rn(sacc[nf][0], sacc[nf][1]);
            const __nv_bfloat162 phi = __floats2bfloat162_rn(sacc[nf][2], sacc[nf][3]);
            *reinterpret_cast<__nv_bfloat162*>(
                smem + 196608 + row0 * 128 + ((chs ^ (row0 & 7)) << 4) + (col & 7) * 2) = plo;
            *reinterpret_cast<__nv_bfloat162*>(
                smem + 196608 + row1 * 128 + ((chs ^ (row1 & 7)) << 4) + (col & 7) * 2) = phi;
        }
        __syncthreads();                                       // [D]
        const float sm0 = redsum[row0] + redsum[64 + row0] +
                          redsum[128 + row0] + redsum[192 + row0];
        const float sm1 = redsum[row1] + redsum[64 + row1] +
                          redsum[128 + row1] + redsum[192 + row1];
        l0 = l0 * f0 + sm0;
        l1 = l1 * f1 + sm1;
        #pragma unroll
        for (int nf = 0; nf < 16; ++nf) {
            oacc[nf][0] *= f0; oacc[nf][1] *= f0;
            oacc[nf][2] *= f1; oacc[nf][3] *= f1;
        }

        // ---- O += P @ V^T ----
        if (t + 1 < 64) {
            asm volatile("cp.async.wait_group 1;" ::: "memory");  // V ready
        } else {
            asm volatile("cp.async.wait_group 0;" ::: "memory");
        }
        __syncthreads();                                       // [E]
        #pragma unroll
        for (int ks = 0; ks < 4; ++ks) {
            uint32_t a[4];
            {
                const int row = wm * 16 + rowA;
                const int ch  = (2 * ks + jA) ^ (row & 7);
                ldsm_x4(a, sP + (uint32_t)(row * 128 + (ch << 4)));
            }
            #pragma unroll
            for (int f2 = 0; f2 < 8; ++f2) {
                const int row = wn * 128 + f2 * 16 + rowB;
                const int ch  = (2 * ks + jB) ^ (row & 7);
                uint32_t tv[4];
                ldsm_x4(tv, sV + (uint32_t)(row * 128 + (ch << 4)));
                uint32_t b0[2] = {tv[0], tv[1]}, b1[2] = {tv[2], tv[3]};
                mma_bf16(oacc[f2 * 2], a, b0);
                mma_bf16(oacc[f2 * 2 + 1], a, b1);
            }
        }
        __syncthreads();                                       // [F] boundary
    }

    // ---- epilogue: normalize + store ----
    const float inv0 = 1.f / l0, inv1 = 1.f / l1;
    #pragma unroll
    for (int nf = 0; nf < 16; ++nf) {
        const int col = wn * 128 + nf * 8 + (l & 3) * 2;
        const __nv_bfloat162 lo =
            __floats2bfloat162_rn(oacc[nf][0] * inv0, oacc[nf][1] * inv0);
        const __nv_bfloat162 hi =
            __floats2bfloat162_rn(oacc[nf][2] * inv1, oacc[nf][3] * inv1);
        *reinterpret_cast<__nv_bfloat162*>(o + (size_t)(q0 + row0) * 512 + col) = lo;
        *reinterpret_cast<__nv_bfloat162*>(o + (size_t)(q0 + row1) * 512 + col) = hi;
    }
}

// ---------------------------------------------------------------------------
__global__ __launch_bounds__(256) void gn_kernel(const float* __restrict__ x,
                                                 const float* __restrict__ scale,
                                                 const float* __restrict__ bias,
                                                 float* __restrict__ hn) {
    const int b = blockIdx.x / kG;
    const int g = blockIdx.x % kG;
    const size_t base = (size_t)b * kCN + (size_t)g * kCPG * kN;
    const float4* x4 = reinterpret_cast<const float4*>(x + base);
    float4* hn4 = reinterpret_cast<float4*>(hn + base);
    const int nvec = kCPG * kN / 4;

    float s = 0.f, ss = 0.f;
    for (int i = threadIdx.x; i < nvec; i += 256) {
        float4 v = x4[i];
        s  += v.x + v.y + v.z + v.w;
        ss += v.x * v.x + v.y * v.y + v.z * v.z + v.w * v.w;
    }
    __shared__ float smS[8], smSS[8];
    #pragma unroll
    for (int o = 16; o > 0; o >>= 1) {
        s  += __shfl_xor_sync(0xffffffffu, s, o);
        ss += __shfl_xor_sync(0xffffffffu, ss, o);
    }
    if ((threadIdx.x & 31) == 0) { smS[threadIdx.x >> 5] = s; smSS[threadIdx.x >> 5] = ss; }
    __syncthreads();
    float S = 0.f, SS = 0.f;
    #pragma unroll
    for (int i = 0; i < 8; i++) { S += smS[i]; SS += smSS[i]; }
    const float invn = 1.f / (float)(kCPG * kN);
    const float mean = S * invn;
    const float var  = SS * invn - mean * mean;
    const float inv  = rsqrtf(var + 1e-6f);

    for (int i = threadIdx.x; i < nvec; i += 256) {
        const int cl = i / (kN / 4);
        const int c  = g * kCPG + cl;
        const float sc = scale[c] * inv;
        const float bi = bias[c] - mean * sc;
        float4 v = x4[i];
        float4 r;
        r.x = v.x * sc + bi; r.y = v.y * sc + bi;
        r.z = v.z * sc + bi; r.w = v.w * sc + bi;
        hn4[i] = r;
    }
}

__global__ __launch_bounds__(256) void transpose_kernel(const float* __restrict__ src,
                                                        __nv_bfloat16* __restrict__ dst) {
    __shared__ float t[32][33];
    const size_t boff = (size_t)blockIdx.z * kCN;
    const int n0 = blockIdx.x * 32, c0 = blockIdx.y * 32;
    const int tx = threadIdx.x & 31, ty = threadIdx.x >> 5;
    #pragma unroll
    for (int i = 0; i < 4; i++)
        t[ty + i * 8][tx] = src[boff + (size_t)(c0 + ty + i * 8) * kN + n0 + tx];
    __syncthreads();
    #pragma unroll
    for (int i = 0; i < 4; i++)
        dst[boff + (size_t)(n0 + ty + i * 8) * kC + c0 + tx] =
            __float2bfloat16_rn(t[tx][ty + i * 8]);
}

__global__ __launch_bounds__(256) void cvt_kernel(const float* __restrict__ src,
                                                  __nv_bfloat16* __restrict__ dst, int n) {
    const int i = blockIdx.x * 256 + threadIdx.x;
    if (i < n) dst[i] = __float2bfloat16_rn(src[i]);
}

__global__ __launch_bounds__(256) void concat_bias_kernel(const float* __restrict__ a,
                                                          const float* __restrict__ b,
                                                          float* __restrict__ o) {
    const int i = blockIdx.x * 256 + threadIdx.x;
    if (i < 512) o[i] = a[i];
    else if (i < 1024) o[i] = b[i - 512];
}

// ---------------------------------------------------------------------------
extern "C" void kernel_launch(void* const* d_in, const int* in_sizes, int n_in,
                              void* d_out, int out_size) {
    const float* x  = (const float*)d_in[0];
    const float* gs = (const float*)d_in[1];
    const float* gb = (const float*)d_in[2];
    const float* wq = (const float*)d_in[3];
    const float* bq = (const float*)d_in[4];
    const float* wk = (const float*)d_in[5];
    const float* bk = (const float*)d_in[6];
    const float* wv = (const float*)d_in[7];
    const float* bv = (const float*)d_in[8];
    const float* wo = (const float*)d_in[9];
    const float* bo = (const float*)d_in[10];
    float* out = (float*)d_out;

    float *hn, *bqk;
    __nv_bfloat16 *hnT, *qkb, *v, *oT, *wr;
    cudaGetSymbolAddress((void**)&hn,  g_hn);
    cudaGetSymbolAddress((void**)&hnT, g_hnT);
    cudaGetSymbolAddress((void**)&qkb, g_qk);
    cudaGetSymbolAddress((void**)&v,   g_v);
    cudaGetSymbolAddress((void**)&oT,  g_oT);
    cudaGetSymbolAddress((void**)&wr,  g_wr);
    cudaGetSymbolAddress((void**)&bqk, g_bqk);
    __nv_bfloat16* wqr = wr;
    __nv_bfloat16* wkr = wr + (size_t)kC * kC;
    __nv_bfloat16* wvr = wr + 2 * (size_t)kC * kC;
    __nv_bfloat16* wor = wr + 3 * (size_t)kC * kC;

    cudaFuncSetAttribute((const void*)mma_gemm<__nv_bfloat16, true,  false, false>,
                         cudaFuncAttributeMaxDynamicSharedMemorySize, kSmemBytes);
    cudaFuncSetAttribute((const void*)mma_gemm<__nv_bfloat16, false, true,  false>,
                         cudaFuncAttributeMaxDynamicSharedMemorySize, kSmemBytes);
    cudaFuncSetAttribute((const void*)mma_gemm<float,         false, true,  true>,
                         cudaFuncAttributeMaxDynamicSharedMemorySize, kSmemBytes);
    cudaFuncSetAttribute((const void*)flash_kernel,
                         cudaFuncAttributeMaxDynamicSharedMemorySize, kFlashSmem);

    const int ww = kC * kC;
    cvt_kernel<<<(ww + 255) / 256, 256>>>(wq, wqr, ww);
    cvt_kernel<<<(ww + 255) / 256, 256>>>(wk, wkr, ww);
    cvt_kernel<<<(ww + 255) / 256, 256>>>(wv, wvr, ww);
    cvt_kernel<<<(ww + 255) / 256, 256>>>(wo, wor, ww);
    concat_bias_kernel<<<4, 256>>>(bq, bk, bqk);

    gn_kernel<<<kB * kG, 256>>>(x, gs, gb, hn);
    transpose_kernel<<<dim3(kN / 32, kC / 32, kB), 256>>>(hn, hnT);

    // Fused Q|K projection: [4096, 1024] = hn_T @ [wq;wk]^T + [bq;bk]
    const dim3 gQK(1024 / 128, kN / 128, kB);      // (8, 32, 8)
    mma_gemm<__nv_bfloat16, true, false, false><<<gQK, 256, kSmemBytes>>>(
        hnT, kC, kCN, wqr, kC, 0, qkb, 1024, (size_t)kN * 1024,
        kC, 1.f, bqk, nullptr, 0);

    // V: [c, spatial]
    const dim3 gV(kN / 128, kC / 128, kB);
    mma_gemm<__nv_bfloat16, false, true, false><<<gV, 256, kSmemBytes>>>(
        wvr, kC, 0, hnT, kC, kCN, v, kN, kCN, kC, 1.f, bv, nullptr, 0);

    // Fused attention: oT[n, c]
    flash_kernel<<<dim3(kN / 64, kB), 512, kFlashSmem>>>(
        qkb, v, oT, 0.044194173824159216f);

    // out = W_o @ oT^T + bo + x
    mma_gemm<float, false, true, true><<<gV, 256, kSmemBytes>>>(
        wor, kC, 0, oT, kC, kCN, out, kN, kCN, kC, 1.f, bo, x, kCN);
}

// round 9
// speedup vs baseline: 1.5147x; 1.5147x over previous
#include <cuda_runtime.h>
#include <cuda_bf16.h>
#include <cuda_fp16.h>
#include <cstdint>
#include <cstddef>
#include <type_traits>

// ---------------------------------------------------------------------------
// SpatialSelfAttention on GB300 — bf16 mma.sync.m16n8k16 engine (unfused R7
// structure, which beat fused flash), with trimmed memory overheads:
//   - GN stats pass + normalize fused into transpose (no fp32 hn buffer)
//   - fused Q|K projection -> qk [n][1024]
//   - scores stored fp16 (halves score-buffer traffic), probs bf16 in place
// ---------------------------------------------------------------------------

namespace {
constexpr int kB = 8;
constexpr int kC = 512;
constexpr int kN = 4096;
constexpr int kG = 32;
constexpr int kCPG = kC / kG;
constexpr size_t kCN = (size_t)kC * kN;
constexpr size_t kNN = (size_t)kN * kN;
constexpr int kSmemBytes = 2 * 32768;
}

// Scratch
__device__ __nv_bfloat16  g_hnT[kB * kCN];                 // [n][c]
__device__ __nv_bfloat16  g_qk [kB * (size_t)kN * 1024];   // q|k  [n][1024]
__device__ __nv_bfloat16  g_v  [kB * kCN];                 // [c][n]
__device__ __nv_bfloat16  g_oT [kB * kCN];                 // [n][c]
__device__ __half         g_s  [kB * kNN];                 // fp16 scores -> bf16 probs
__device__ __nv_bfloat16  g_wr [4 * kC * kC];              // wq|wk|wv|wo
__device__ float          g_bqk[1024];
__device__ float2         g_stats[kB * kG];                // (mean, rsqrt(var+eps))

// ---------------------------------------------------------------------------
__device__ __forceinline__ uint32_t smem_u32(const void* p) {
    uint32_t a;
    asm("{ .reg .u64 t; cvta.to.shared.u64 t, %1; cvt.u32.u64 %0, t; }"
        : "=r"(a) : "l"(p));
    return a;
}
__device__ __forceinline__ void cp_async16(uint32_t dst, const void* src) {
    asm volatile("cp.async.cg.shared.global [%0], [%1], 16;"
                 :: "r"(dst), "l"(src));
}
__device__ __forceinline__ void ldsm_x4(uint32_t* r, uint32_t addr) {
    asm volatile("ldmatrix.sync.aligned.m8n8.x4.shared.b16 {%0,%1,%2,%3}, [%4];"
                 : "=r"(r[0]), "=r"(r[1]), "=r"(r[2]), "=r"(r[3]) : "r"(addr));
}
__device__ __forceinline__ void mma_bf16(float* d, const uint32_t* a,
                                         const uint32_t* b) {
    asm volatile(
        "mma.sync.aligned.m16n8k16.row.col.f32.bf16.bf16.f32 "
        "{%0,%1,%2,%3}, {%4,%5,%6,%7}, {%8,%9}, {%0,%1,%2,%3};"
        : "+f"(d[0]), "+f"(d[1]), "+f"(d[2]), "+f"(d[3])
        : "r"(a[0]), "r"(a[1]), "r"(a[2]), "r"(a[3]), "r"(b[0]), "r"(b[1]));
}

// ---------------------------------------------------------------------------
// bf16 GEMM: D[m,n] = alpha * sum_k A[m,k]*B[n,k] (+bias)(+resid)
// A: K-major [M,K]; B: K-major [N,K]; C row-major [M,ldc] OutT.
// 128x128x64 tiles, double-buffered cp.async, 8 warps (4m x 2n).
// ---------------------------------------------------------------------------
template <typename OutT, bool BIAS_N, bool BIAS_M, bool RESID>
__global__ __launch_bounds__(256)
void mma_gemm(const __nv_bfloat16* __restrict__ A, int lda, size_t sA,
              const __nv_bfloat16* __restrict__ B, int ldb, size_t sB,
              OutT* __restrict__ C, int ldc, size_t sC,
              int K, float alpha,
              const float* __restrict__ bias,
              const float* __restrict__ resid, size_t sR)
{
    extern __shared__ char smem[];
    const uint32_t base = smem_u32(smem);

    const int tid = threadIdx.x;
    const int wid = tid >> 5;
    const int l   = tid & 31;
    const int wm  = wid & 3;
    const int wn  = wid >> 2;

    A += (size_t)blockIdx.z * sA;
    B += (size_t)blockIdx.z * sB;
    C += (size_t)blockIdx.z * sC;
    if (RESID) resid += (size_t)blockIdx.z * sR;

    const int bm = blockIdx.y * 128;
    const int bn = blockIdx.x * 128;

    const int rowA = (l & 7) + ((l >> 3) & 1) * 8;
    const int jA   = (l >> 4) & 1;
    const int rowB = (l & 7) + ((l >> 4) & 1) * 8;
    const int jB   = (l >> 3) & 1;

    float acc[2][8][4];
    #pragma unroll
    for (int i = 0; i < 2; i++)
        #pragma unroll
        for (int j = 0; j < 8; j++)
            #pragma unroll
            for (int r = 0; r < 4; r++) acc[i][j][r] = 0.f;

    const int nk = K >> 6;

    auto load_tile = [&](int it, int s) {
        const uint32_t aB = base + s * 32768;
        const uint32_t bB = aB + 16384;
        const __nv_bfloat16* ag = A + (size_t)bm * lda + (it << 6);
        const __nv_bfloat16* bg = B + (size_t)bn * ldb + (it << 6);
        #pragma unroll
        for (int i = 0; i < 4; ++i) {
            const int idx = tid + (i << 8);
            const int r = idx >> 3, c = idx & 7;
            const uint32_t so = (uint32_t)(r * 128 + ((c ^ (r & 7)) << 4));
            cp_async16(aB + so, ag + (size_t)r * lda + c * 8);
            cp_async16(bB + so, bg + (size_t)r * ldb + c * 8);
        }
        asm volatile("cp.async.commit_group;" ::: "memory");
    };

    load_tile(0, 0);
    for (int it = 0; it < nk; ++it) {
        if (it + 1 < nk) {
            load_tile(it + 1, (it + 1) & 1);
            asm volatile("cp.async.wait_group 1;" ::: "memory");
        } else {
            asm volatile("cp.async.wait_group 0;" ::: "memory");
        }
        __syncthreads();

        const uint32_t aB = base + (it & 1) * 32768;
        const uint32_t bB = aB + 16384;

        #pragma unroll
        for (int ks = 0; ks < 4; ++ks) {
            uint32_t afr[2][4];
            #pragma unroll
            for (int fm = 0; fm < 2; ++fm) {
                const int row = wm * 32 + fm * 16 + rowA;
                const int ch  = (2 * ks + jA) ^ (row & 7);
                ldsm_x4(afr[fm], aB + (uint32_t)(row * 128 + (ch << 4)));
            }
            uint32_t bfr[8][2];
            #pragma unroll
            for (int f2 = 0; f2 < 4; ++f2) {
                const int row = wn * 64 + f2 * 16 + rowB;
                const int ch  = (2 * ks + jB) ^ (row & 7);
                uint32_t t[4];
                ldsm_x4(t, bB + (uint32_t)(row * 128 + (ch << 4)));
                bfr[f2 * 2][0]     = t[0]; bfr[f2 * 2][1]     = t[1];
                bfr[f2 * 2 + 1][0] = t[2]; bfr[f2 * 2 + 1][1] = t[3];
            }
            #pragma unroll
            for (int fm = 0; fm < 2; ++fm)
                #pragma unroll
                for (int fn = 0; fn < 8; ++fn)
                    mma_bf16(acc[fm][fn], afr[fm], bfr[fn]);
        }
        __syncthreads();
    }

    #pragma unroll
    for (int fm = 0; fm < 2; ++fm) {
        const int r0 = bm + wm * 32 + fm * 16 + (l >> 2);
        #pragma unroll
        for (int half = 0; half < 2; ++half) {
            const int m = r0 + half * 8;
            const float bmv = BIAS_M ? bias[m] : 0.f;
            #pragma unroll
            for (int fn = 0; fn < 8; ++fn) {
                const int col = bn + wn * 64 + fn * 8 + (l & 3) * 2;
                float2 o;
                o.x = acc[fm][fn][half * 2 + 0] * alpha;
                o.y = acc[fm][fn][half * 2 + 1] * alpha;
                if (BIAS_N) { o.x += bias[col]; o.y += bias[col + 1]; }
                if (BIAS_M) { o.x += bmv; o.y += bmv; }
                if (RESID) {
                    const float2 rv = *reinterpret_cast<const float2*>(
                        &resid[(size_t)m * ldc + col]);
                    o.x += rv.x; o.y += rv.y;
                }
                OutT* dst = &C[(size_t)m * ldc + col];
                if constexpr (std::is_same_v<OutT, float>) {
                    *reinterpret_cast<float2*>(dst) = o;
                } else if constexpr (std::is_same_v<OutT, __half>) {
                    *reinterpret_cast<__half2*>(dst) = __floats2half2_rn(o.x, o.y);
                } else {
                    *reinterpret_cast<__nv_bfloat162*>(dst) =
                        __floats2bfloat162_rn(o.x, o.y);
                }
            }
        }
    }
}

// ---------------------------------------------------------------------------
// GroupNorm stats only: one block per (batch, group) -> (mean, rsqrt(var+eps))
// ---------------------------------------------------------------------------
__global__ __launch_bounds__(256) void gn_stats_kernel(const float* __restrict__ x,
                                                       float2* __restrict__ stats) {
    const int b = blockIdx.x / kG;
    const int g = blockIdx.x % kG;
    const size_t base = (size_t)b * kCN + (size_t)g * kCPG * kN;
    const float4* x4 = reinterpret_cast<const float4*>(x + base);
    const int nvec = kCPG * kN / 4;

    float s = 0.f, ss = 0.f;
    for (int i = threadIdx.x; i < nvec; i += 256) {
        float4 v = x4[i];
        s  += v.x + v.y + v.z + v.w;
        ss += v.x * v.x + v.y * v.y + v.z * v.z + v.w * v.w;
    }
    __shared__ float smS[8], smSS[8];
    #pragma unroll
    for (int o = 16; o > 0; o >>= 1) {
        s  += __shfl_xor_sync(0xffffffffu, s, o);
        ss += __shfl_xor_sync(0xffffffffu, ss, o);
    }
    if ((threadIdx.x & 31) == 0) { smS[threadIdx.x >> 5] = s; smSS[threadIdx.x >> 5] = ss; }
    __syncthreads();
    if (threadIdx.x == 0) {
        float S = 0.f, SS = 0.f;
        #pragma unroll
        for (int i = 0; i < 8; i++) { S += smS[i]; SS += smSS[i]; }
        const float invn = 1.f / (float)(kCPG * kN);
        const float mean = S * invn;
        const float var  = SS * invn - mean * mean;
        stats[blockIdx.x] = make_float2(mean, rsqrtf(var + 1e-6f));
    }
}

// ---------------------------------------------------------------------------
// Fused normalize + transpose: x [c][n] fp32 -> hnT [n][c] bf16
// ---------------------------------------------------------------------------
__global__ __launch_bounds__(256) void transnorm_kernel(
    const float* __restrict__ x, const float2* __restrict__ stats,
    const float* __restrict__ scale, const float* __restrict__ bias,
    __nv_bfloat16* __restrict__ dst)
{
    __shared__ float t[32][33];
    const int bz = blockIdx.z;
    const size_t boff = (size_t)bz * kCN;
    const int n0 = blockIdx.x * 32, c0 = blockIdx.y * 32;
    const int tx = threadIdx.x & 31, ty = threadIdx.x >> 5;
    #pragma unroll
    for (int i = 0; i < 4; i++)
        t[ty + i * 8][tx] = x[boff + (size_t)(c0 + ty + i * 8) * kN + n0 + tx];
    __syncthreads();
    const int c = c0 + tx;
    const float2 st = stats[bz * kG + (c >> 4)];   // kCPG = 16
    const float sc = scale[c] * st.y;
    const float bi = bias[c] - st.x * sc;
    #pragma unroll
    for (int i = 0; i < 4; i++)
        dst[boff + (size_t)(n0 + ty + i * 8) * kC + c] =
            __float2bfloat16_rn(t[tx][ty + i * 8] * sc + bi);
}

// ---------------------------------------------------------------------------
// All four weight matrices -> bf16 in one launch. n = 4 * 512 * 512.
// ---------------------------------------------------------------------------
__global__ __launch_bounds__(256) void cvt4_kernel(
    const float* __restrict__ wq, const float* __restrict__ wk,
    const float* __restrict__ wv, const float* __restrict__ wo,
    __nv_bfloat16* __restrict__ dst)
{
    const int i = blockIdx.x * 256 + threadIdx.x;     // < 1048576
    const int sel = i >> 18;                          // 262144 per matrix
    const int off = i & 0x3FFFF;
    const float* src = (sel == 0) ? wq : (sel == 1) ? wk : (sel == 2) ? wv : wo;
    dst[i] = __float2bfloat16_rn(src[off]);
}

__global__ __launch_bounds__(256) void concat_bias_kernel(const float* __restrict__ a,
                                                          const float* __restrict__ b,
                                                          float* __restrict__ o) {
    const int i = blockIdx.x * 256 + threadIdx.x;
    if (i < 512) o[i] = a[i];
    else if (i < 1024) o[i] = b[i - 512];
}

// ---------------------------------------------------------------------------
// In-place softmax: row of 4096 fp16 logits -> 4096 bf16 probs (same bytes).
// All reads complete before first __syncthreads; writes after final reduce.
// ---------------------------------------------------------------------------
__global__ __launch_bounds__(256) void softmax_kernel(__half* __restrict__ s) {
    __half* row = s + ((size_t)blockIdx.y * kN + (size_t)blockIdx.x) * kN;
    uint4* r4 = reinterpret_cast<uint4*>(row);

    uint4 raw[2];
    float f[16];
    float mx = -3.402823e38f;
    #pragma unroll
    for (int i = 0; i < 2; i++) {
        raw[i] = r4[threadIdx.x + i * 256];
        const __half2* h2 = reinterpret_cast<const __half2*>(&raw[i]);
        #pragma unroll
        for (int j = 0; j < 4; j++) {
            const float2 v = __half22float2(h2[j]);
            f[i * 8 + j * 2]     = v.x;
            f[i * 8 + j * 2 + 1] = v.y;
            mx = fmaxf(mx, fmaxf(v.x, v.y));
        }
    }

    __shared__ float sm[8];
    #pragma unroll
    for (int o = 16; o > 0; o >>= 1)
        mx = fmaxf(mx, __shfl_xor_sync(0xffffffffu, mx, o));
    if ((threadIdx.x & 31) == 0) sm[threadIdx.x >> 5] = mx;
    __syncthreads();
    float m = sm[0];
    #pragma unroll
    for (int i = 1; i < 8; i++) m = fmaxf(m, sm[i]);
    __syncthreads();

    float sum = 0.f;
    #pragma unroll
    for (int i = 0; i < 16; i++) {
        f[i] = __expf(f[i] - m);
        sum += f[i];
    }
    #pragma unroll
    for (int o = 16; o > 0; o >>= 1)
        sum += __shfl_xor_sync(0xffffffffu, sum, o);
    if ((threadIdx.x & 31) == 0) sm[threadIdx.x >> 5] = sum;
    __syncthreads();
    float tot = 0.f;
    #pragma unroll
    for (int i = 0; i < 8; i++) tot += sm[i];
    const float inv = 1.f / tot;

    uint4* o4 = reinterpret_cast<uint4*>(row);
    #pragma unroll
    for (int i = 0; i < 2; i++) {
        uint4 val;
        __nv_bfloat162* b2 = reinterpret_cast<__nv_bfloat162*>(&val);
        #pragma unroll
        for (int j = 0; j < 4; j++)
            b2[j] = __floats2bfloat162_rn(f[i * 8 + j * 2] * inv,
                                          f[i * 8 + j * 2 + 1] * inv);
        o4[threadIdx.x + i * 256] = val;
    }
}

// ---------------------------------------------------------------------------
extern "C" void kernel_launch(void* const* d_in, const int* in_sizes, int n_in,
                              void* d_out, int out_size) {
    const float* x  = (const float*)d_in[0];
    const float* gs = (const float*)d_in[1];
    const float* gb = (const float*)d_in[2];
    const float* wq = (const float*)d_in[3];
    const float* bq = (const float*)d_in[4];
    const float* wk = (const float*)d_in[5];
    const float* bk = (const float*)d_in[6];
    const float* wv = (const float*)d_in[7];
    const float* bv = (const float*)d_in[8];
    const float* wo = (const float*)d_in[9];
    const float* bo = (const float*)d_in[10];
    float* out = (float*)d_out;

    __nv_bfloat16 *hnT, *qkb, *v, *oT, *wr;
    __half* s;
    float* bqk;
    float2* stats;
    cudaGetSymbolAddress((void**)&hnT,   g_hnT);
    cudaGetSymbolAddress((void**)&qkb,   g_qk);
    cudaGetSymbolAddress((void**)&v,     g_v);
    cudaGetSymbolAddress((void**)&oT,    g_oT);
    cudaGetSymbolAddress((void**)&s,     g_s);
    cudaGetSymbolAddress((void**)&wr,    g_wr);
    cudaGetSymbolAddress((void**)&bqk,   g_bqk);
    cudaGetSymbolAddress((void**)&stats, g_stats);
    __nv_bfloat16* wvr = wr + 2 * (size_t)kC * kC;
    __nv_bfloat16* wor = wr + 3 * (size_t)kC * kC;

    cudaFuncSetAttribute((const void*)mma_gemm<__nv_bfloat16, true,  false, false>,
                         cudaFuncAttributeMaxDynamicSharedMemorySize, kSmemBytes);
    cudaFuncSetAttribute((const void*)mma_gemm<__nv_bfloat16, false, true,  false>,
                         cudaFuncAttributeMaxDynamicSharedMemorySize, kSmemBytes);
    cudaFuncSetAttribute((const void*)mma_gemm<__half,        false, false, false>,
                         cudaFuncAttributeMaxDynamicSharedMemorySize, kSmemBytes);
    cudaFuncSetAttribute((const void*)mma_gemm<__nv_bfloat16, false, false, false>,
                         cudaFuncAttributeMaxDynamicSharedMemorySize, kSmemBytes);
    cudaFuncSetAttribute((const void*)mma_gemm<float,         false, true,  true>,
                         cudaFuncAttributeMaxDynamicSharedMemorySize, kSmemBytes);

    cvt4_kernel<<<4096, 256>>>(wq, wk, wv, wo, wr);
    concat_bias_kernel<<<4, 256>>>(bq, bk, bqk);
    gn_stats_kernel<<<kB * kG, 256>>>(x, stats);
    transnorm_kernel<<<dim3(kN / 32, kC / 32, kB), 256>>>(x, stats, gs, gb, hnT);

    // Fused Q|K projection: [4096, 1024] = hn_T @ [wq;wk]^T + [bq;bk]
    const dim3 gQKp(1024 / 128, kN / 128, kB);
    mma_gemm<__nv_bfloat16, true, false, false><<<gQKp, 256, kSmemBytes>>>(
        hnT, kC, kCN, wr, kC, 0, qkb, 1024, (size_t)kN * 1024,
        kC, 1.f, bqk, nullptr, 0);

    // V: [c, spatial]
    const dim3 gV(kN / 128, kC / 128, kB);
    mma_gemm<__nv_bfloat16, false, true, false><<<gV, 256, kSmemBytes>>>(
        wvr, kC, 0, hnT, kC, kCN, v, kN, kCN, kC, 1.f, bv, nullptr, 0);

    // scores[i,j] = (q[i,:] . k[j,:]) / sqrt(C)  -> fp16
    const dim3 gS(kN / 128, kN / 128, kB);
    mma_gemm<__half, false, false, false><<<gS, 256, kSmemBytes>>>(
        qkb, 1024, (size_t)kN * 1024, qkb + 512, 1024, (size_t)kN * 1024,
        s, kN, kNN, kC, 0.044194173824159216f, nullptr, nullptr, 0);

    // softmax: fp16 logits -> bf16 probs in place
    softmax_kernel<<<dim3(kN, kB), 256>>>(s);

    // oT[i,c] = sum_j P[i,j] * v[c,j]
    const __nv_bfloat16* probs = reinterpret_cast<const __nv_bfloat16*>(s);
    const dim3 gO(kC / 128, kN / 128, kB);
    mma_gemm<__nv_bfloat16, false, false, false><<<gO, 256, kSmemBytes>>>(
        probs, kN, kNN, v, kN, kCN, oT, kC, kCN, kN, 1.f, nullptr, nullptr, 0);

    // out = W_o @ oT^T + bo + x
    mma_gemm<float, false, true, true><<<gV, 256, kSmemBytes>>>(
        wor, kC, 0, oT, kC, kCN, out, kN, kCN, kC, 1.f, bo, x, kCN);
}